// round 1
// baseline (speedup 1.0000x reference)
#include <cuda_runtime.h>

#define BWIN 2048
#define NTOK 128
#define DIM 128
#define HEADS 4
#define HD 32
#define SCALE 0.17677669529663687f

// Scratch (device globals; no allocation allowed)
__device__ float g_q[BWIN*HEADS*NTOK*HD];
__device__ float g_k[BWIN*HEADS*NTOK*HD];
__device__ float g_v[BWIN*HEADS*NTOK*HD];
__device__ float g_o[(size_t)BWIN*NTOK*DIM];
__device__ float g_rpb[HEADS*NTOK*NTOK];
__device__ float g_cmask[256*NTOK*NTOK];

// ---------------------------------------------------------------------------
// prep: combined additive mask (sp_mask + mask share index b%256) and
// gathered relative-position bias rpb[h][n][m] = table[rpi[n][m]*H + h]
// ---------------------------------------------------------------------------
__global__ void prep_k(const int* __restrict__ rpi,
                       const float* __restrict__ mask,
                       const float* __restrict__ sp,
                       const float* __restrict__ table) {
    int i = blockIdx.x * 256 + threadIdx.x;   // grid covers 256*16384 exactly
    g_cmask[i] = mask[i] + sp[i];
    if (i < HEADS * NTOK * NTOK) {
        int h = i >> 14, r = i & 16383;
        g_rpb[i] = table[rpi[r] * HEADS + h];
    }
}

// ---------------------------------------------------------------------------
// GEMM: C[M x Ncols] = A[M x 128] @ W[Ncols x 128]^T + bias
// Block tile 128x64, 256 threads, 8x4 microtile, K chunked by 32.
// MODE 0: qkv projection -> scatter into g_q (scaled), g_k, g_v
// MODE 1: out projection (A = g_o) -> Out
// ---------------------------------------------------------------------------
template<int MODE>
__global__ __launch_bounds__(256) void gemm_k(const float* __restrict__ A,
                                              const float* __restrict__ W,
                                              const float* __restrict__ bias,
                                              float* __restrict__ Out) {
    __shared__ float As[128][33];
    __shared__ float Bs[64][33];

    const float* Ap = (MODE == 1) ? (const float*)g_o : A;

    int rb = blockIdx.x, cb = blockIdx.y;
    int tid = threadIdx.x;
    int tx = tid & 15, ty = tid >> 4;

    float acc[8][4];
#pragma unroll
    for (int i = 0; i < 8; i++)
#pragma unroll
        for (int j = 0; j < 4; j++) acc[i][j] = 0.f;

    const float* Ab = Ap + (size_t)rb * 128 * 128;
    const float* Wb = W + (size_t)cb * 64 * 128;

    for (int kk = 0; kk < 128; kk += 32) {
#pragma unroll
        for (int i = 0; i < 16; i++) {
            int e = tid + i * 256;
            int r = e >> 5, c = e & 31;
            As[r][c] = Ab[(size_t)r * 128 + kk + c];
        }
#pragma unroll
        for (int i = 0; i < 8; i++) {
            int e = tid + i * 256;
            int r = e >> 5, c = e & 31;
            Bs[r][c] = Wb[(size_t)r * 128 + kk + c];
        }
        __syncthreads();
#pragma unroll
        for (int k = 0; k < 32; k++) {
            float a[8], b[4];
#pragma unroll
            for (int i = 0; i < 8; i++) a[i] = As[ty * 8 + i][k];
#pragma unroll
            for (int j = 0; j < 4; j++) b[j] = Bs[tx * 4 + j][k];
#pragma unroll
            for (int i = 0; i < 8; i++)
#pragma unroll
                for (int j = 0; j < 4; j++) acc[i][j] += a[i] * b[j];
        }
        __syncthreads();
    }

#pragma unroll
    for (int i = 0; i < 8; i++) {
        int row = rb * 128 + ty * 8 + i;
#pragma unroll
        for (int j = 0; j < 4; j++) {
            int col = cb * 64 + tx * 4 + j;
            float val = acc[i][j] + bias[col];
            if (MODE == 0) {
                int part = col >> 7, rem = col & 127;
                int h = rem >> 5, d = rem & 31;
                int b_ = row >> 7, n = row & 127;
                size_t off = (((size_t)(b_ * HEADS + h)) * 128 + n) * 32 + d;
                if (part == 0)      g_q[off] = val * SCALE;
                else if (part == 1) g_k[off] = val;
                else                g_v[off] = val;
            } else {
                Out[(size_t)row * 128 + col] = val;
            }
        }
    }
}

// ---------------------------------------------------------------------------
// Attention: one CTA per (b, h). Q,K(transposed),V,S all in smem (116 KB).
// Phase 1: S = Q@K^T + rpb + cmask (4x4 microtile, float4 K loads)
// Phase 2: warp-per-row softmax
// Phase 3: O = P@V (4-row microtile, lane = head dim)
// ---------------------------------------------------------------------------
__global__ __launch_bounds__(512) void attn_k() {
    extern __shared__ float sm[];
    float* Qs  = sm;           // [128][33]  = 4224
    float* KsT = sm + 4224;    // [32][132]  = 4224
    float* Vs  = sm + 8448;    // [128][33]  = 4224
    float* S   = sm + 12672;   // [128][128] = 16384

    int bh = blockIdx.x;
    int b = bh >> 2, h = bh & 3;
    const float* q = g_q + (size_t)bh * 4096;
    const float* k = g_k + (size_t)bh * 4096;
    const float* v = g_v + (size_t)bh * 4096;

    int tid = threadIdx.x;
    for (int e = tid; e < 4096; e += 512) {
        int n = e >> 5, d = e & 31;
        Qs[n * 33 + d]  = q[e];
        Vs[n * 33 + d]  = v[e];
        KsT[d * 132 + n] = k[e];
    }
    __syncthreads();

    const float* rpb = g_rpb + (size_t)h * 16384;
    const float* cm  = g_cmask + (size_t)(b & 255) * 16384;

    // Phase 1: 1024 (4x4) tiles over 128x128 S
    for (int t = tid; t < 1024; t += 512) {
        int n0 = (t >> 5) << 2, m0 = (t & 31) << 2;
        float a00=0,a01=0,a02=0,a03=0, a10=0,a11=0,a12=0,a13=0;
        float a20=0,a21=0,a22=0,a23=0, a30=0,a31=0,a32=0,a33=0;
#pragma unroll
        for (int d = 0; d < 32; d++) {
            float4 kv = *(const float4*)(KsT + d * 132 + m0);
            float q0 = Qs[(n0 + 0) * 33 + d];
            float q1 = Qs[(n0 + 1) * 33 + d];
            float q2 = Qs[(n0 + 2) * 33 + d];
            float q3 = Qs[(n0 + 3) * 33 + d];
            a00 += q0*kv.x; a01 += q0*kv.y; a02 += q0*kv.z; a03 += q0*kv.w;
            a10 += q1*kv.x; a11 += q1*kv.y; a12 += q1*kv.z; a13 += q1*kv.w;
            a20 += q2*kv.x; a21 += q2*kv.y; a22 += q2*kv.z; a23 += q2*kv.w;
            a30 += q3*kv.x; a31 += q3*kv.y; a32 += q3*kv.z; a33 += q3*kv.w;
        }
        float r0[4] = {a00,a01,a02,a03};
        float r1[4] = {a10,a11,a12,a13};
        float r2[4] = {a20,a21,a22,a23};
        float r3[4] = {a30,a31,a32,a33};
        float* rows[4] = {r0, r1, r2, r3};
#pragma unroll
        for (int i = 0; i < 4; i++) {
            int base = (n0 + i) * 128 + m0;
            float4 rb4 = *(const float4*)(rpb + base);
            float4 cb4 = *(const float4*)(cm + base);
            float4 o;
            o.x = rows[i][0] + rb4.x + cb4.x;
            o.y = rows[i][1] + rb4.y + cb4.y;
            o.z = rows[i][2] + rb4.z + cb4.z;
            o.w = rows[i][3] + rb4.w + cb4.w;
            *(float4*)(S + base) = o;
        }
    }
    __syncthreads();

    // Phase 2: softmax, warp per row (16 warps x 8 rows)
    int warp = tid >> 5, lane = tid & 31;
    for (int n = warp; n < 128; n += 16) {
        float x0 = S[n * 128 + lane];
        float x1 = S[n * 128 + lane + 32];
        float x2 = S[n * 128 + lane + 64];
        float x3 = S[n * 128 + lane + 96];
        float mx = fmaxf(fmaxf(x0, x1), fmaxf(x2, x3));
#pragma unroll
        for (int o = 16; o > 0; o >>= 1)
            mx = fmaxf(mx, __shfl_xor_sync(0xffffffffu, mx, o));
        float e0 = __expf(x0 - mx), e1 = __expf(x1 - mx);
        float e2 = __expf(x2 - mx), e3 = __expf(x3 - mx);
        float s = e0 + e1 + e2 + e3;
#pragma unroll
        for (int o = 16; o > 0; o >>= 1)
            s += __shfl_xor_sync(0xffffffffu, s, o);
        float inv = 1.0f / s;
        S[n * 128 + lane]      = e0 * inv;
        S[n * 128 + lane + 32] = e1 * inv;
        S[n * 128 + lane + 64] = e2 * inv;
        S[n * 128 + lane + 96] = e3 * inv;
    }
    __syncthreads();

    // Phase 3: O = P@V, 4 rows per warp-iteration, lane = d
    for (int g = warp; g < 32; g += 16) {
        int n0 = g << 2;
        float a0 = 0.f, a1 = 0.f, a2 = 0.f, a3 = 0.f;
#pragma unroll 4
        for (int m = 0; m < 128; m++) {
            float vv = Vs[m * 33 + lane];
            a0 += S[(n0 + 0) * 128 + m] * vv;
            a1 += S[(n0 + 1) * 128 + m] * vv;
            a2 += S[(n0 + 2) * 128 + m] * vv;
            a3 += S[(n0 + 3) * 128 + m] * vv;
        }
        size_t ob = ((size_t)b * 128) * 128 + (size_t)h * 32 + lane;
        g_o[ob + (size_t)(n0 + 0) * 128] = a0;
        g_o[ob + (size_t)(n0 + 1) * 128] = a1;
        g_o[ob + (size_t)(n0 + 2) * 128] = a2;
        g_o[ob + (size_t)(n0 + 3) * 128] = a3;
    }
}

// ---------------------------------------------------------------------------
extern "C" void kernel_launch(void* const* d_in, const int* in_sizes, int n_in,
                              void* d_out, int out_size) {
    const float* x      = (const float*)d_in[0];
    const int*   rpi    = (const int*)d_in[1];
    const float* mask   = (const float*)d_in[2];
    const float* sp     = (const float*)d_in[3];
    const float* w_qkv  = (const float*)d_in[4];
    const float* b_qkv  = (const float*)d_in[5];
    const float* table  = (const float*)d_in[6];
    const float* w_proj = (const float*)d_in[7];
    const float* b_proj = (const float*)d_in[8];
    float* out = (float*)d_out;

    // 1) masks + rpb
    prep_k<<<16384, 256>>>(rpi, mask, sp, table);

    // 2) QKV projection: M=262144, N=384, K=128
    gemm_k<0><<<dim3(2048, 6), 256>>>(x, w_qkv, b_qkv, nullptr);

    // 3) attention per (b, h)
    const int ATTN_SMEM = 29056 * 4;  // 116224 bytes
    cudaFuncSetAttribute(attn_k, cudaFuncAttributeMaxDynamicSharedMemorySize,
                         ATTN_SMEM);
    attn_k<<<BWIN * HEADS, 512, ATTN_SMEM>>>();

    // 4) output projection: M=262144, N=128, K=128
    gemm_k<1><<<dim3(2048, 2), 256>>>(nullptr, w_proj, b_proj, out);
}

// round 2
// speedup vs baseline: 1.2151x; 1.2151x over previous
#include <cuda_runtime.h>
#include <cuda_bf16.h>
#include <cstdint>

#define BWIN 2048
#define NTOK 128
#define DIM 128
#define HEADS 4
#define HD 32
#define SCALE 0.17677669529663687f

// Scratch (device globals; no allocation allowed)
__device__ float g_q[BWIN*HEADS*NTOK*HD];
__device__ float g_k[BWIN*HEADS*NTOK*HD];
__device__ float g_v[BWIN*HEADS*NTOK*HD];
__device__ float g_o[(size_t)BWIN*NTOK*DIM];
__device__ float g_rpb[HEADS*NTOK*NTOK];
__device__ float g_cmask[256*NTOK*NTOK];

// ---------------------------------------------------------------------------
// prep: combined additive mask (sp_mask + mask share index b%256) and
// gathered relative-position bias rpb[h][n][m] = table[rpi[n][m]*H + h]
// ---------------------------------------------------------------------------
__global__ void prep_k(const int* __restrict__ rpi,
                       const float* __restrict__ mask,
                       const float* __restrict__ sp,
                       const float* __restrict__ table) {
    int i = blockIdx.x * 256 + threadIdx.x;
    g_cmask[i] = mask[i] + sp[i];
    if (i < HEADS * NTOK * NTOK) {
        int h = i >> 14, r = i & 16383;
        g_rpb[i] = table[rpi[r] * HEADS + h];
    }
}

// ---------------------------------------------------------------------------
// Tensor-core GEMM with bf16 split precision:
//   C = A @ W^T + bias, where A fp32 is split A = Ah + Al (bf16 each),
//   C = Ah Wh + Ah Wl + Al Wh  (error ~2^-18, fp32 accumulate).
// Block tile 128 x 128, 256 threads (8 warps, 4x2 warp grid, 32x64 per warp),
// whole K=128 staged in smem once (no k-chunk loop).
// MODE 0: qkv projection -> scatter into g_q (scaled), g_k, g_v
// MODE 1: out projection (A = g_o) -> Out
// ---------------------------------------------------------------------------
#define LDS_STRIDE 136   // 128 + 8 elems: bank = (4g+q) mod 32, conflict-free

__device__ __forceinline__ void mma16816(float* d, const uint32_t* a,
                                         const uint32_t* b) {
    asm volatile(
        "mma.sync.aligned.m16n8k16.row.col.f32.bf16.bf16.f32 "
        "{%0,%1,%2,%3}, {%4,%5,%6,%7}, {%8,%9}, {%0,%1,%2,%3};\n"
        : "+f"(d[0]), "+f"(d[1]), "+f"(d[2]), "+f"(d[3])
        : "r"(a[0]), "r"(a[1]), "r"(a[2]), "r"(a[3]),
          "r"(b[0]), "r"(b[1]));
}

__device__ __forceinline__ void split_store(__nv_bfloat16* hi, __nv_bfloat16* lo,
                                            int idx, float v) {
    __nv_bfloat16 h = __float2bfloat16_rn(v);
    float hf = __bfloat162float(h);
    hi[idx] = h;
    lo[idx] = __float2bfloat16_rn(v - hf);
}

template<int MODE>
__global__ __launch_bounds__(256) void gemm_mma(const float* __restrict__ A,
                                                const float* __restrict__ W,
                                                const float* __restrict__ bias,
                                                float* __restrict__ Out) {
    extern __shared__ __nv_bfloat16 sh[];
    __nv_bfloat16* Ah = sh;
    __nv_bfloat16* Al = sh + 128 * LDS_STRIDE;
    __nv_bfloat16* Wh = sh + 2 * 128 * LDS_STRIDE;
    __nv_bfloat16* Wl = sh + 3 * 128 * LDS_STRIDE;

    const float* Ap = (MODE == 1) ? (const float*)g_o : A;

    int rb = blockIdx.x, cb = blockIdx.y;
    int tid = threadIdx.x;
    int warp = tid >> 5, lane = tid & 31;
    int g = lane >> 2, q = lane & 3;
    int wr = (warp >> 1) * 32;   // warp row offset (0,32,64,96)
    int wc = (warp & 1) * 64;    // warp col offset (0,64)

    const float* Ab = Ap + (size_t)rb * 128 * 128;
    const float* Wb = W + (size_t)cb * 128 * 128;

    // Load + split-convert A and W tiles (float4 coalesced)
#pragma unroll
    for (int i = 0; i < 16; i++) {
        int idx = tid + i * 256;           // 4096 float4s
        int r = idx >> 5, c4 = (idx & 31) << 2;
        float4 av = *(const float4*)(Ab + (size_t)r * 128 + c4);
        int base = r * LDS_STRIDE + c4;
        split_store(Ah, Al, base + 0, av.x);
        split_store(Ah, Al, base + 1, av.y);
        split_store(Ah, Al, base + 2, av.z);
        split_store(Ah, Al, base + 3, av.w);
        float4 wv = *(const float4*)(Wb + (size_t)r * 128 + c4);
        split_store(Wh, Wl, base + 0, wv.x);
        split_store(Wh, Wl, base + 1, wv.y);
        split_store(Wh, Wl, base + 2, wv.z);
        split_store(Wh, Wl, base + 3, wv.w);
    }
    __syncthreads();

    float acc[2][8][4];
#pragma unroll
    for (int mt = 0; mt < 2; mt++)
#pragma unroll
        for (int nt = 0; nt < 8; nt++)
#pragma unroll
            for (int e = 0; e < 4; e++) acc[mt][nt][e] = 0.f;

#pragma unroll
    for (int ks = 0; ks < 8; ks++) {
        int kk = ks * 16;
        uint32_t ah[2][4], al[2][4];
#pragma unroll
        for (int mt = 0; mt < 2; mt++) {
            int r0 = wr + mt * 16 + g;
            const __nv_bfloat16* p0 = Ah + r0 * LDS_STRIDE + kk + 2 * q;
            const __nv_bfloat16* p1 = Ah + (r0 + 8) * LDS_STRIDE + kk + 2 * q;
            ah[mt][0] = *(const uint32_t*)p0;
            ah[mt][1] = *(const uint32_t*)p1;
            ah[mt][2] = *(const uint32_t*)(p0 + 8);
            ah[mt][3] = *(const uint32_t*)(p1 + 8);
            const __nv_bfloat16* q0 = Al + r0 * LDS_STRIDE + kk + 2 * q;
            const __nv_bfloat16* q1 = Al + (r0 + 8) * LDS_STRIDE + kk + 2 * q;
            al[mt][0] = *(const uint32_t*)q0;
            al[mt][1] = *(const uint32_t*)q1;
            al[mt][2] = *(const uint32_t*)(q0 + 8);
            al[mt][3] = *(const uint32_t*)(q1 + 8);
        }
#pragma unroll
        for (int nt = 0; nt < 8; nt++) {
            int n = wc + nt * 8 + g;
            const __nv_bfloat16* pb = Wh + n * LDS_STRIDE + kk + 2 * q;
            const __nv_bfloat16* pl = Wl + n * LDS_STRIDE + kk + 2 * q;
            uint32_t bh[2], bl[2];
            bh[0] = *(const uint32_t*)pb;
            bh[1] = *(const uint32_t*)(pb + 8);
            bl[0] = *(const uint32_t*)pl;
            bl[1] = *(const uint32_t*)(pl + 8);
#pragma unroll
            for (int mt = 0; mt < 2; mt++) {
                mma16816(acc[mt][nt], ah[mt], bh);
                mma16816(acc[mt][nt], ah[mt], bl);
                mma16816(acc[mt][nt], al[mt], bh);
            }
        }
    }

    // Epilogue
#pragma unroll
    for (int mt = 0; mt < 2; mt++) {
#pragma unroll
        for (int nt = 0; nt < 8; nt++) {
#pragma unroll
            for (int e = 0; e < 4; e++) {
                int row = rb * 128 + wr + mt * 16 + g + (e >> 1) * 8;
                int col = cb * 128 + wc + nt * 8 + 2 * q + (e & 1);
                float val = acc[mt][nt][e] + bias[col];
                if (MODE == 0) {
                    int part = col >> 7, rem = col & 127;
                    int h = rem >> 5, d = rem & 31;
                    int b_ = row >> 7, n = row & 127;
                    size_t off = (((size_t)(b_ * HEADS + h)) * 128 + n) * 32 + d;
                    if (part == 0)      g_q[off] = val * SCALE;
                    else if (part == 1) g_k[off] = val;
                    else                g_v[off] = val;
                } else {
                    Out[(size_t)row * 128 + col] = val;
                }
            }
        }
    }
}

// ---------------------------------------------------------------------------
// Attention: one CTA per (b, h). Q,K(transposed),V,S all in smem (116 KB).
// ---------------------------------------------------------------------------
__global__ __launch_bounds__(512) void attn_k() {
    extern __shared__ float sm[];
    float* Qs  = sm;           // [128][33]  = 4224
    float* KsT = sm + 4224;    // [32][132]  = 4224
    float* Vs  = sm + 8448;    // [128][33]  = 4224
    float* S   = sm + 12672;   // [128][128] = 16384

    int bh = blockIdx.x;
    int b = bh >> 2, h = bh & 3;
    const float* q = g_q + (size_t)bh * 4096;
    const float* k = g_k + (size_t)bh * 4096;
    const float* v = g_v + (size_t)bh * 4096;

    int tid = threadIdx.x;
    for (int e = tid; e < 4096; e += 512) {
        int n = e >> 5, d = e & 31;
        Qs[n * 33 + d]  = q[e];
        Vs[n * 33 + d]  = v[e];
        KsT[d * 132 + n] = k[e];
    }
    __syncthreads();

    const float* rpb = g_rpb + (size_t)h * 16384;
    const float* cm  = g_cmask + (size_t)(b & 255) * 16384;

    for (int t = tid; t < 1024; t += 512) {
        int n0 = (t >> 5) << 2, m0 = (t & 31) << 2;
        float a00=0,a01=0,a02=0,a03=0, a10=0,a11=0,a12=0,a13=0;
        float a20=0,a21=0,a22=0,a23=0, a30=0,a31=0,a32=0,a33=0;
#pragma unroll
        for (int d = 0; d < 32; d++) {
            float4 kv = *(const float4*)(KsT + d * 132 + m0);
            float q0 = Qs[(n0 + 0) * 33 + d];
            float q1 = Qs[(n0 + 1) * 33 + d];
            float q2 = Qs[(n0 + 2) * 33 + d];
            float q3 = Qs[(n0 + 3) * 33 + d];
            a00 += q0*kv.x; a01 += q0*kv.y; a02 += q0*kv.z; a03 += q0*kv.w;
            a10 += q1*kv.x; a11 += q1*kv.y; a12 += q1*kv.z; a13 += q1*kv.w;
            a20 += q2*kv.x; a21 += q2*kv.y; a22 += q2*kv.z; a23 += q2*kv.w;
            a30 += q3*kv.x; a31 += q3*kv.y; a32 += q3*kv.z; a33 += q3*kv.w;
        }
        float r0[4] = {a00,a01,a02,a03};
        float r1[4] = {a10,a11,a12,a13};
        float r2[4] = {a20,a21,a22,a23};
        float r3[4] = {a30,a31,a32,a33};
        float* rows[4] = {r0, r1, r2, r3};
#pragma unroll
        for (int i = 0; i < 4; i++) {
            int base = (n0 + i) * 128 + m0;
            float4 rb4 = *(const float4*)(rpb + base);
            float4 cb4 = *(const float4*)(cm + base);
            float4 o;
            o.x = rows[i][0] + rb4.x + cb4.x;
            o.y = rows[i][1] + rb4.y + cb4.y;
            o.z = rows[i][2] + rb4.z + cb4.z;
            o.w = rows[i][3] + rb4.w + cb4.w;
            *(float4*)(S + base) = o;
        }
    }
    __syncthreads();

    int warp = tid >> 5, lane = tid & 31;
    for (int n = warp; n < 128; n += 16) {
        float x0 = S[n * 128 + lane];
        float x1 = S[n * 128 + lane + 32];
        float x2 = S[n * 128 + lane + 64];
        float x3 = S[n * 128 + lane + 96];
        float mx = fmaxf(fmaxf(x0, x1), fmaxf(x2, x3));
#pragma unroll
        for (int o = 16; o > 0; o >>= 1)
            mx = fmaxf(mx, __shfl_xor_sync(0xffffffffu, mx, o));
        float e0 = __expf(x0 - mx), e1 = __expf(x1 - mx);
        float e2 = __expf(x2 - mx), e3 = __expf(x3 - mx);
        float s = e0 + e1 + e2 + e3;
#pragma unroll
        for (int o = 16; o > 0; o >>= 1)
            s += __shfl_xor_sync(0xffffffffu, s, o);
        float inv = 1.0f / s;
        S[n * 128 + lane]      = e0 * inv;
        S[n * 128 + lane + 32] = e1 * inv;
        S[n * 128 + lane + 64] = e2 * inv;
        S[n * 128 + lane + 96] = e3 * inv;
    }
    __syncthreads();

    for (int g2 = warp; g2 < 32; g2 += 16) {
        int n0 = g2 << 2;
        float a0 = 0.f, a1 = 0.f, a2 = 0.f, a3 = 0.f;
#pragma unroll 4
        for (int m = 0; m < 128; m++) {
            float vv = Vs[m * 33 + lane];
            a0 += S[(n0 + 0) * 128 + m] * vv;
            a1 += S[(n0 + 1) * 128 + m] * vv;
            a2 += S[(n0 + 2) * 128 + m] * vv;
            a3 += S[(n0 + 3) * 128 + m] * vv;
        }
        size_t ob = ((size_t)b * 128) * 128 + (size_t)h * 32 + lane;
        g_o[ob + (size_t)(n0 + 0) * 128] = a0;
        g_o[ob + (size_t)(n0 + 1) * 128] = a1;
        g_o[ob + (size_t)(n0 + 2) * 128] = a2;
        g_o[ob + (size_t)(n0 + 3) * 128] = a3;
    }
}

// ---------------------------------------------------------------------------
extern "C" void kernel_launch(void* const* d_in, const int* in_sizes, int n_in,
                              void* d_out, int out_size) {
    const float* x      = (const float*)d_in[0];
    const int*   rpi    = (const int*)d_in[1];
    const float* mask   = (const float*)d_in[2];
    const float* sp     = (const float*)d_in[3];
    const float* w_qkv  = (const float*)d_in[4];
    const float* b_qkv  = (const float*)d_in[5];
    const float* table  = (const float*)d_in[6];
    const float* w_proj = (const float*)d_in[7];
    const float* b_proj = (const float*)d_in[8];
    float* out = (float*)d_out;

    const int GEMM_SMEM = 4 * 128 * LDS_STRIDE * 2;  // 139264 bytes
    cudaFuncSetAttribute(gemm_mma<0>, cudaFuncAttributeMaxDynamicSharedMemorySize,
                         GEMM_SMEM);
    cudaFuncSetAttribute(gemm_mma<1>, cudaFuncAttributeMaxDynamicSharedMemorySize,
                         GEMM_SMEM);
    const int ATTN_SMEM = 29056 * 4;  // 116224 bytes
    cudaFuncSetAttribute(attn_k, cudaFuncAttributeMaxDynamicSharedMemorySize,
                         ATTN_SMEM);

    // 1) masks + rpb
    prep_k<<<16384, 256>>>(rpi, mask, sp, table);

    // 2) QKV projection: M=262144, N=384, K=128 (tensor cores, bf16 split)
    gemm_mma<0><<<dim3(2048, 3), 256, GEMM_SMEM>>>(x, w_qkv, b_qkv, nullptr);

    // 3) attention per (b, h)
    attn_k<<<BWIN * HEADS, 512, ATTN_SMEM>>>();

    // 4) output projection: M=262144, N=128, K=128 (tensor cores, bf16 split)
    gemm_mma<1><<<dim3(2048, 1), 256, GEMM_SMEM>>>(nullptr, w_proj, b_proj, out);
}

// round 4
// speedup vs baseline: 2.0113x; 1.6553x over previous
#include <cuda_runtime.h>
#include <cuda_bf16.h>
#include <cstdint>

#define BWIN 2048
#define NTOK 128
#define DIM 128
#define HEADS 4
#define HD 32
#define SCALE 0.17677669529663687f

// Scratch (device globals; no allocation allowed)
__device__ float g_q[BWIN*HEADS*NTOK*HD];
__device__ float g_k[BWIN*HEADS*NTOK*HD];
__device__ float g_v[BWIN*HEADS*NTOK*HD];
__device__ float g_o[(size_t)BWIN*NTOK*DIM];
__device__ float g_rpb[HEADS*NTOK*NTOK];
__device__ float g_cmask[256*NTOK*NTOK];

// ---------------------------------------------------------------------------
__global__ void prep_k(const int* __restrict__ rpi,
                       const float* __restrict__ mask,
                       const float* __restrict__ sp,
                       const float* __restrict__ table) {
    int i = blockIdx.x * 256 + threadIdx.x;
    g_cmask[i] = mask[i] + sp[i];
    if (i < HEADS * NTOK * NTOK) {
        int h = i >> 14, r = i & 16383;
        g_rpb[i] = table[rpi[r] * HEADS + h];
    }
}

// ---------------------------------------------------------------------------
// bf16 split-precision mma helpers
// ---------------------------------------------------------------------------
__device__ __forceinline__ void mma16816(float* d, const uint32_t* a,
                                         const uint32_t* b) {
    asm volatile(
        "mma.sync.aligned.m16n8k16.row.col.f32.bf16.bf16.f32 "
        "{%0,%1,%2,%3}, {%4,%5,%6,%7}, {%8,%9}, {%0,%1,%2,%3};\n"
        : "+f"(d[0]), "+f"(d[1]), "+f"(d[2]), "+f"(d[3])
        : "r"(a[0]), "r"(a[1]), "r"(a[2]), "r"(a[3]),
          "r"(b[0]), "r"(b[1]));
}

__device__ __forceinline__ void split_store(__nv_bfloat16* hi, __nv_bfloat16* lo,
                                            int idx, float v) {
    __nv_bfloat16 h = __float2bfloat16_rn(v);
    float hf = __bfloat162float(h);
    hi[idx] = h;
    lo[idx] = __float2bfloat16_rn(v - hf);
}

// ---------------------------------------------------------------------------
// Projection GEMM (unchanged from R2, proven correct/fast)
// ---------------------------------------------------------------------------
#define LDS_STRIDE 136

template<int MODE>
__global__ __launch_bounds__(256) void gemm_mma(const float* __restrict__ A,
                                                const float* __restrict__ W,
                                                const float* __restrict__ bias,
                                                float* __restrict__ Out) {
    extern __shared__ __nv_bfloat16 sh[];
    __nv_bfloat16* Ah = sh;
    __nv_bfloat16* Al = sh + 128 * LDS_STRIDE;
    __nv_bfloat16* Wh = sh + 2 * 128 * LDS_STRIDE;
    __nv_bfloat16* Wl = sh + 3 * 128 * LDS_STRIDE;

    const float* Ap = (MODE == 1) ? (const float*)g_o : A;

    int rb = blockIdx.x, cb = blockIdx.y;
    int tid = threadIdx.x;
    int warp = tid >> 5, lane = tid & 31;
    int g = lane >> 2, q = lane & 3;
    int wr = (warp >> 1) * 32;
    int wc = (warp & 1) * 64;

    const float* Ab = Ap + (size_t)rb * 128 * 128;
    const float* Wb = W + (size_t)cb * 128 * 128;

#pragma unroll
    for (int i = 0; i < 16; i++) {
        int idx = tid + i * 256;
        int r = idx >> 5, c4 = (idx & 31) << 2;
        float4 av = *(const float4*)(Ab + (size_t)r * 128 + c4);
        int base = r * LDS_STRIDE + c4;
        split_store(Ah, Al, base + 0, av.x);
        split_store(Ah, Al, base + 1, av.y);
        split_store(Ah, Al, base + 2, av.z);
        split_store(Ah, Al, base + 3, av.w);
        float4 wv = *(const float4*)(Wb + (size_t)r * 128 + c4);
        split_store(Wh, Wl, base + 0, wv.x);
        split_store(Wh, Wl, base + 1, wv.y);
        split_store(Wh, Wl, base + 2, wv.z);
        split_store(Wh, Wl, base + 3, wv.w);
    }
    __syncthreads();

    float acc[2][8][4];
#pragma unroll
    for (int mt = 0; mt < 2; mt++)
#pragma unroll
        for (int nt = 0; nt < 8; nt++)
#pragma unroll
            for (int e = 0; e < 4; e++) acc[mt][nt][e] = 0.f;

#pragma unroll
    for (int ks = 0; ks < 8; ks++) {
        int kk = ks * 16;
        uint32_t ah[2][4], al[2][4];
#pragma unroll
        for (int mt = 0; mt < 2; mt++) {
            int r0 = wr + mt * 16 + g;
            const __nv_bfloat16* p0 = Ah + r0 * LDS_STRIDE + kk + 2 * q;
            const __nv_bfloat16* p1 = Ah + (r0 + 8) * LDS_STRIDE + kk + 2 * q;
            ah[mt][0] = *(const uint32_t*)p0;
            ah[mt][1] = *(const uint32_t*)p1;
            ah[mt][2] = *(const uint32_t*)(p0 + 8);
            ah[mt][3] = *(const uint32_t*)(p1 + 8);
            const __nv_bfloat16* q0 = Al + r0 * LDS_STRIDE + kk + 2 * q;
            const __nv_bfloat16* q1 = Al + (r0 + 8) * LDS_STRIDE + kk + 2 * q;
            al[mt][0] = *(const uint32_t*)q0;
            al[mt][1] = *(const uint32_t*)q1;
            al[mt][2] = *(const uint32_t*)(q0 + 8);
            al[mt][3] = *(const uint32_t*)(q1 + 8);
        }
#pragma unroll
        for (int nt = 0; nt < 8; nt++) {
            int n = wc + nt * 8 + g;
            const __nv_bfloat16* pb = Wh + n * LDS_STRIDE + kk + 2 * q;
            const __nv_bfloat16* pl = Wl + n * LDS_STRIDE + kk + 2 * q;
            uint32_t bh[2], bl[2];
            bh[0] = *(const uint32_t*)pb;
            bh[1] = *(const uint32_t*)(pb + 8);
            bl[0] = *(const uint32_t*)pl;
            bl[1] = *(const uint32_t*)(pl + 8);
#pragma unroll
            for (int mt = 0; mt < 2; mt++) {
                mma16816(acc[mt][nt], ah[mt], bh);
                mma16816(acc[mt][nt], ah[mt], bl);
                mma16816(acc[mt][nt], al[mt], bh);
            }
        }
    }

#pragma unroll
    for (int mt = 0; mt < 2; mt++) {
#pragma unroll
        for (int nt = 0; nt < 8; nt++) {
#pragma unroll
            for (int e = 0; e < 4; e++) {
                int row = rb * 128 + wr + mt * 16 + g + (e >> 1) * 8;
                int col = cb * 128 + wc + nt * 8 + 2 * q + (e & 1);
                float val = acc[mt][nt][e] + bias[col];
                if (MODE == 0) {
                    int part = col >> 7, rem = col & 127;
                    int h = rem >> 5, d = rem & 31;
                    int b_ = row >> 7, n = row & 127;
                    size_t off = (((size_t)(b_ * HEADS + h)) * 128 + n) * 32 + d;
                    if (part == 0)      g_q[off] = val * SCALE;
                    else if (part == 1) g_k[off] = val;
                    else                g_v[off] = val;
                } else {
                    Out[(size_t)row * 128 + col] = val;
                }
            }
        }
    }
}

// ---------------------------------------------------------------------------
// Tensor-core attention: one CTA per (b, h), 512 threads (16 warps, 8x2 grid).
// Phase 1: S = Q@K^T + rpb + cmask  (bf16 split, 3 MMAs)
// Phase 2: warp-per-row softmax, writes P as bf16 hi/lo
// Phase 3: O = P@V  (bf16 split, 3 MMAs, V pre-transposed)
// ---------------------------------------------------------------------------
#define QK_STR 40    // bf16 stride for Q/K tiles (128x32): banks (20g+q)%32 bijective
#define P_STR 136    // bf16 stride for P (128x128) and V^T (32x128): (4g+q)%32 bijective
#define S_STR 132    // fp32 stride for S

#define OFF_QH 0
#define OFF_QL 10240
#define OFF_KH 20480
#define OFF_KL 30720
#define OFF_VH 40960
#define OFF_VL 49664
#define OFF_S  58368
#define OFF_PH 125952
#define OFF_PL 160768
#define ATTN_SMEM 195584

__global__ __launch_bounds__(512) void attn_mma() {
    extern __shared__ char smraw[];
    __nv_bfloat16* Qh  = (__nv_bfloat16*)(smraw + OFF_QH);
    __nv_bfloat16* Ql  = (__nv_bfloat16*)(smraw + OFF_QL);
    __nv_bfloat16* Kh  = (__nv_bfloat16*)(smraw + OFF_KH);
    __nv_bfloat16* Kl  = (__nv_bfloat16*)(smraw + OFF_KL);
    __nv_bfloat16* VhT = (__nv_bfloat16*)(smraw + OFF_VH);
    __nv_bfloat16* VlT = (__nv_bfloat16*)(smraw + OFF_VL);
    float*         S   = (float*)(smraw + OFF_S);
    __nv_bfloat16* Ph  = (__nv_bfloat16*)(smraw + OFF_PH);
    __nv_bfloat16* Pl  = (__nv_bfloat16*)(smraw + OFF_PL);

    int bh = blockIdx.x;
    int b = bh >> 2, h = bh & 3;
    const float* qg = g_q + (size_t)bh * 4096;
    const float* kg = g_k + (size_t)bh * 4096;
    const float* vg = g_v + (size_t)bh * 4096;

    int tid = threadIdx.x;
    int warp = tid >> 5, lane = tid & 31;
    int g = lane >> 2, q2 = (lane & 3) * 2;
    int wm = warp & 7, wn = warp >> 3;   // 8x2 warp grid
    int r0 = wm * 16;

    // Phase 0: load + split q,k (row-major) and v (transposed)
#pragma unroll
    for (int i = tid; i < 1024; i += 512) {
        int n = i >> 3, d4 = (i & 7) << 2;
        float4 qv = *(const float4*)(qg + n * 32 + d4);
        float4 kv = *(const float4*)(kg + n * 32 + d4);
        float4 vv = *(const float4*)(vg + n * 32 + d4);
        int base = n * QK_STR + d4;
        split_store(Qh, Ql, base + 0, qv.x);
        split_store(Qh, Ql, base + 1, qv.y);
        split_store(Qh, Ql, base + 2, qv.z);
        split_store(Qh, Ql, base + 3, qv.w);
        split_store(Kh, Kl, base + 0, kv.x);
        split_store(Kh, Kl, base + 1, kv.y);
        split_store(Kh, Kl, base + 2, kv.z);
        split_store(Kh, Kl, base + 3, kv.w);
        split_store(VhT, VlT, (d4 + 0) * P_STR + n, vv.x);
        split_store(VhT, VlT, (d4 + 1) * P_STR + n, vv.y);
        split_store(VhT, VlT, (d4 + 2) * P_STR + n, vv.z);
        split_store(VhT, VlT, (d4 + 3) * P_STR + n, vv.w);
    }
    __syncthreads();

    // Phase 1: S = Q K^T + biases. Warp tile 16 x 64.
    {
        float acc[8][4];
#pragma unroll
        for (int nt = 0; nt < 8; nt++)
#pragma unroll
            for (int e = 0; e < 4; e++) acc[nt][e] = 0.f;

#pragma unroll
        for (int ks = 0; ks < 2; ks++) {
            int kk = ks * 16;
            uint32_t ah[4], al[4];
            {
                const __nv_bfloat16* p0 = Qh + (r0 + g) * QK_STR + kk + q2;
                const __nv_bfloat16* p1 = Qh + (r0 + 8 + g) * QK_STR + kk + q2;
                ah[0] = *(const uint32_t*)p0;
                ah[1] = *(const uint32_t*)p1;
                ah[2] = *(const uint32_t*)(p0 + 8);
                ah[3] = *(const uint32_t*)(p1 + 8);
                const __nv_bfloat16* l0 = Ql + (r0 + g) * QK_STR + kk + q2;
                const __nv_bfloat16* l1 = Ql + (r0 + 8 + g) * QK_STR + kk + q2;
                al[0] = *(const uint32_t*)l0;
                al[1] = *(const uint32_t*)l1;
                al[2] = *(const uint32_t*)(l0 + 8);
                al[3] = *(const uint32_t*)(l1 + 8);
            }
#pragma unroll
            for (int nt = 0; nt < 8; nt++) {
                int n = wn * 64 + nt * 8 + g;
                const __nv_bfloat16* pb = Kh + n * QK_STR + kk + q2;
                const __nv_bfloat16* pl = Kl + n * QK_STR + kk + q2;
                uint32_t bh2[2], bl2[2];
                bh2[0] = *(const uint32_t*)pb;
                bh2[1] = *(const uint32_t*)(pb + 8);
                bl2[0] = *(const uint32_t*)pl;
                bl2[1] = *(const uint32_t*)(pl + 8);
                mma16816(acc[nt], ah, bh2);
                mma16816(acc[nt], ah, bl2);
                mma16816(acc[nt], al, bh2);
            }
        }

        // epilogue: add rpb + cmask, write S
        const float* rpb = g_rpb + (size_t)h * 16384;
        const float* cm  = g_cmask + (size_t)(b & 255) * 16384;
#pragma unroll
        for (int nt = 0; nt < 8; nt++) {
            int col = wn * 64 + nt * 8 + q2;
#pragma unroll
            for (int half = 0; half < 2; half++) {
                int row = r0 + g + half * 8;
                float2 rb2 = *(const float2*)(rpb + row * 128 + col);
                float2 cm2 = *(const float2*)(cm + row * 128 + col);
                float2 o;
                o.x = acc[nt][half * 2 + 0] + rb2.x + cm2.x;
                o.y = acc[nt][half * 2 + 1] + rb2.y + cm2.y;
                *(float2*)(S + row * S_STR + col) = o;
            }
        }
    }
    __syncthreads();

    // Phase 2: softmax (warp per row), write P bf16 hi/lo
    for (int n = warp; n < 128; n += 16) {
        float x0 = S[n * S_STR + lane];
        float x1 = S[n * S_STR + lane + 32];
        float x2 = S[n * S_STR + lane + 64];
        float x3 = S[n * S_STR + lane + 96];
        float mx = fmaxf(fmaxf(x0, x1), fmaxf(x2, x3));
#pragma unroll
        for (int o = 16; o > 0; o >>= 1)
            mx = fmaxf(mx, __shfl_xor_sync(0xffffffffu, mx, o));
        float e0 = __expf(x0 - mx), e1 = __expf(x1 - mx);
        float e2 = __expf(x2 - mx), e3 = __expf(x3 - mx);
        float s = e0 + e1 + e2 + e3;
#pragma unroll
        for (int o = 16; o > 0; o >>= 1)
            s += __shfl_xor_sync(0xffffffffu, s, o);
        float inv = 1.0f / s;
        split_store(Ph, Pl, n * P_STR + lane,      e0 * inv);
        split_store(Ph, Pl, n * P_STR + lane + 32, e1 * inv);
        split_store(Ph, Pl, n * P_STR + lane + 64, e2 * inv);
        split_store(Ph, Pl, n * P_STR + lane + 96, e3 * inv);
    }
    __syncthreads();

    // Phase 3: O = P V. Warp tile 16 rows x 16 d-cols (2 n-tiles).
    {
        float acc[2][4];
#pragma unroll
        for (int nt = 0; nt < 2; nt++)
#pragma unroll
            for (int e = 0; e < 4; e++) acc[nt][e] = 0.f;

#pragma unroll
        for (int ks = 0; ks < 8; ks++) {
            int kk = ks * 16;
            uint32_t ah[4], al[4];
            {
                const __nv_bfloat16* p0 = Ph + (r0 + g) * P_STR + kk + q2;
                const __nv_bfloat16* p1 = Ph + (r0 + 8 + g) * P_STR + kk + q2;
                ah[0] = *(const uint32_t*)p0;
                ah[1] = *(const uint32_t*)p1;
                ah[2] = *(const uint32_t*)(p0 + 8);
                ah[3] = *(const uint32_t*)(p1 + 8);
                const __nv_bfloat16* l0 = Pl + (r0 + g) * P_STR + kk + q2;
                const __nv_bfloat16* l1 = Pl + (r0 + 8 + g) * P_STR + kk + q2;
                al[0] = *(const uint32_t*)l0;
                al[1] = *(const uint32_t*)l1;
                al[2] = *(const uint32_t*)(l0 + 8);
                al[3] = *(const uint32_t*)(l1 + 8);
            }
#pragma unroll
            for (int nt = 0; nt < 2; nt++) {
                int nd = wn * 16 + nt * 8 + g;    // d index 0..31
                const __nv_bfloat16* pb = VhT + nd * P_STR + kk + q2;
                const __nv_bfloat16* pl = VlT + nd * P_STR + kk + q2;
                uint32_t bh2[2], bl2[2];
                bh2[0] = *(const uint32_t*)pb;
                bh2[1] = *(const uint32_t*)(pb + 8);
                bl2[0] = *(const uint32_t*)pl;
                bl2[1] = *(const uint32_t*)(pl + 8);
                mma16816(acc[nt], ah, bh2);
                mma16816(acc[nt], ah, bl2);
                mma16816(acc[nt], al, bh2);
            }
        }

        // write O to g_o[b][n][h*32 + d]
        float* ob = g_o + (size_t)b * 16384 + h * 32;
#pragma unroll
        for (int nt = 0; nt < 2; nt++) {
            int d = wn * 16 + nt * 8 + q2;
#pragma unroll
            for (int half = 0; half < 2; half++) {
                int row = r0 + g + half * 8;
                float2 o;
                o.x = acc[nt][half * 2 + 0];
                o.y = acc[nt][half * 2 + 1];
                *(float2*)(ob + (size_t)row * 128 + d) = o;
            }
        }
    }
}

// ---------------------------------------------------------------------------
extern "C" void kernel_launch(void* const* d_in, const int* in_sizes, int n_in,
                              void* d_out, int out_size) {
    const float* x      = (const float*)d_in[0];
    const int*   rpi    = (const int*)d_in[1];
    const float* mask   = (const float*)d_in[2];
    const float* sp     = (const float*)d_in[3];
    const float* w_qkv  = (const float*)d_in[4];
    const float* b_qkv  = (const float*)d_in[5];
    const float* table  = (const float*)d_in[6];
    const float* w_proj = (const float*)d_in[7];
    const float* b_proj = (const float*)d_in[8];
    float* out = (float*)d_out;

    const int GEMM_SMEM = 4 * 128 * LDS_STRIDE * 2;  // 139264 bytes
    cudaFuncSetAttribute(gemm_mma<0>, cudaFuncAttributeMaxDynamicSharedMemorySize,
                         GEMM_SMEM);
    cudaFuncSetAttribute(gemm_mma<1>, cudaFuncAttributeMaxDynamicSharedMemorySize,
                         GEMM_SMEM);
    cudaFuncSetAttribute(attn_mma, cudaFuncAttributeMaxDynamicSharedMemorySize,
                         ATTN_SMEM);

    // 1) masks + rpb
    prep_k<<<16384, 256>>>(rpi, mask, sp, table);

    // 2) QKV projection: M=262144, N=384, K=128
    gemm_mma<0><<<dim3(2048, 3), 256, GEMM_SMEM>>>(x, w_qkv, b_qkv, nullptr);

    // 3) attention per (b, h), tensor cores
    attn_mma<<<BWIN * HEADS, 512, ATTN_SMEM>>>();

    // 4) output projection: M=262144, N=128, K=128
    gemm_mma<1><<<dim3(2048, 1), 256, GEMM_SMEM>>>(nullptr, w_proj, b_proj, out);
}